// round 15
// baseline (speedup 1.0000x reference)
#include <cuda_runtime.h>
#include <cuda_fp16.h>
#include <math.h>

#define N_NODES 100000
#define N_EDGES 800000
#define VOCAB   256
#define DIM     256
#define N_MASK  10000
#define R2      16
#define SCAN_B  1024
#define NBLK    ((N_NODES + SCAN_B - 1) / SCAN_B)   // 98
#define SAGG_STRIDE 10
#define EW_ROWS 4                                    // vocab rows per ew1 block

// ---------------- zeroed-per-run region (single memset) ----------------
struct ZeroRegion {
    int deg[N_NODES];
    unsigned char need[N_NODES];
};
__device__ ZeroRegion g_z;

// ---------------- other scratch ----------------
__device__ float g_dinv[N_NODES];
__device__ int   g_rowstart[N_NODES + 1];
__device__ int   g_cursor[N_NODES];
__device__ int2  g_csr[N_EDGES];          // .x = src | (x[src]<<20), .y = norm weight bits
__device__ int   g_blocksum[NBLK];
__device__ int   g_blockoff[NBLK];
__device__ uint4 g_EW1h[VOCAB * 32];              // fp16 EW1: 128 KB
__device__ uint4 g_h1h[(size_t)N_NODES * 32];     // fp16 h1 rows (512 B each)

// ---------------- helpers ----------------
__device__ __forceinline__ unsigned long long pk2(float x, float y) {
    unsigned long long r;
    asm("mov.b64 %0, {%1,%2};" : "=l"(r) : "f"(x), "f"(y));
    return r;
}
__device__ __forceinline__ float2 upk2(unsigned long long v) {
    float2 f;
    asm("mov.b64 {%0,%1}, %2;" : "=f"(f.x), "=f"(f.y) : "l"(v));
    return f;
}
__device__ __forceinline__ void fma2p(unsigned long long& d,
                                      unsigned long long a,
                                      unsigned long long b) {
    asm("fma.rn.f32x2 %0, %1, %2, %0;" : "+l"(d) : "l"(a), "l"(b));
}
__device__ __forceinline__ int warp_incl_scan(int v, int lane) {
#pragma unroll
    for (int off = 1; off < 32; off <<= 1) {
        int n = __shfl_up_sync(0xFFFFFFFFu, v, off);
        if (lane >= off) v += n;
    }
    return v;
}
__device__ __forceinline__ void acc8(float2& a0, float2& a1, float2& a2, float2& a3,
                                     float w, uint4 r) {
    float2 f0 = __half22float2(*reinterpret_cast<__half2*>(&r.x));
    float2 f1 = __half22float2(*reinterpret_cast<__half2*>(&r.y));
    float2 f2 = __half22float2(*reinterpret_cast<__half2*>(&r.z));
    float2 f3 = __half22float2(*reinterpret_cast<__half2*>(&r.w));
    a0.x = fmaf(w, f0.x, a0.x); a0.y = fmaf(w, f0.y, a0.y);
    a1.x = fmaf(w, f1.x, a1.x); a1.y = fmaf(w, f1.y, a1.y);
    a2.x = fmaf(w, f2.x, a2.x); a2.y = fmaf(w, f2.y, a2.y);
    a3.x = fmaf(w, f3.x, a3.x); a3.y = fmaf(w, f3.y, a3.y);
}

// ---------------- CSR construction ----------------
__global__ void k_hist(const int* __restrict__ dst) {
    int i = blockIdx.x * blockDim.x + threadIdx.x;
    if (i < N_EDGES) atomicAdd(&g_z.deg[dst[i]], 1);
}

__global__ void __launch_bounds__(SCAN_B) k_blocksum() {
    __shared__ int wsum[32];
    const int t    = threadIdx.x;
    const int lane = t & 31;
    const int wid  = t >> 5;
    const int i    = blockIdx.x * SCAN_B + t;
    int v = (i < N_NODES) ? g_z.deg[i] : 0;
#pragma unroll
    for (int off = 16; off > 0; off >>= 1) v += __shfl_xor_sync(0xFFFFFFFFu, v, off);
    if (lane == 0) wsum[wid] = v;
    __syncthreads();
    if (wid == 0) {
        int s = wsum[lane];
#pragma unroll
        for (int off = 16; off > 0; off >>= 1) s += __shfl_xor_sync(0xFFFFFFFFu, s, off);
        if (lane == 0) g_blocksum[blockIdx.x] = s;
    }
}

__global__ void k_scanblocks() {
    __shared__ int ws[4];
    const int t    = threadIdx.x;     // 128 threads
    const int lane = t & 31;
    const int wid  = t >> 5;
    int v = (t < NBLK) ? g_blocksum[t] : 0;
    int incl = warp_incl_scan(v, lane);
    if (lane == 31) ws[wid] = incl;
    __syncthreads();
    if (t == 0) {
        int run = 0;
#pragma unroll
        for (int w = 0; w < 4; w++) { int tmp = ws[w]; ws[w] = run; run += tmp; }
    }
    __syncthreads();
    if (t < NBLK) g_blockoff[t] = incl - v + ws[wid];
}

__global__ void __launch_bounds__(SCAN_B) k_scanfinal() {
    __shared__ int wsum[32];
    const int t    = threadIdx.x;
    const int lane = t & 31;
    const int wid  = t >> 5;
    const int i    = blockIdx.x * SCAN_B + t;
    const int cnt  = (i < N_NODES) ? g_z.deg[i] : 0;
    int incl = warp_incl_scan(cnt, lane);
    if (lane == 31) wsum[wid] = incl;
    __syncthreads();
    if (wid == 0) wsum[lane] = warp_incl_scan(wsum[lane], lane);
    __syncthreads();
    int excl = incl - cnt + (wid ? wsum[wid - 1] : 0) + g_blockoff[blockIdx.x];
    if (i < N_NODES) {
        g_rowstart[i] = excl;
        g_cursor[i]   = excl;
        g_dinv[i]     = rsqrtf((float)(cnt + 1));
        if (i == N_NODES - 1) g_rowstart[N_NODES] = excl + cnt;
    }
}

__global__ void k_fill(const int* __restrict__ src, const int* __restrict__ dst,
                       const int* __restrict__ x) {
    int i = blockIdx.x * blockDim.x + threadIdx.x;
    if (i < N_EDGES) {
        int s = src[i];
        int d = dst[i];
        float w = g_dinv[s] * g_dinv[d];
        int p = atomicAdd(&g_cursor[d], 1);
        g_csr[p] = make_int2(s | (x[s] << 20), __float_as_int(w));
    }
}

__global__ void k_mark(const int* __restrict__ mask) {
    const int w = blockIdx.x * (blockDim.x >> 5) + (threadIdx.x >> 5);
    if (w >= N_MASK) return;
    const int lane = threadIdx.x & 31;
    const int m = mask[w];
    if (lane == 0) g_z.need[m] = 1;
    const int e0 = g_rowstart[m];
    const int e1 = g_rowstart[m + 1];
    for (int e = e0 + lane; e < e1; e += 32) g_z.need[g_csr[e].x & 0xFFFFF] = 1;
}

// ---------------- EW1 = emb @ W1 -> fp16; 4 rows/block for W1 reuse --------
__global__ void __launch_bounds__(DIM) k_ew1(const float* __restrict__ emb,
                                             const float* __restrict__ W1) {
    __shared__ float se[EW_ROWS][DIM];
    const int v0 = blockIdx.x * EW_ROWS;
    const int c  = threadIdx.x;
#pragma unroll
    for (int r = 0; r < EW_ROWS; r++) se[r][c] = emb[(v0 + r) * DIM + c];
    __syncthreads();
    float acc[EW_ROWS] = {0.f, 0.f, 0.f, 0.f};
#pragma unroll 4
    for (int k = 0; k < DIM; k++) {
        const float w = W1[k * DIM + c];
#pragma unroll
        for (int r = 0; r < EW_ROWS; r++) acc[r] = fmaf(se[r][k], w, acc[r]);
    }
    __half* E = reinterpret_cast<__half*>(g_EW1h);
#pragma unroll
    for (int r = 0; r < EW_ROWS; r++) E[(v0 + r) * DIM + c] = __float2half(acc[r]);
}

// ---------------- layer 1: warp/node, edge loop unrolled x2 ----------------
__global__ void k_layer1(const int* __restrict__ x, const float* __restrict__ b1) {
    const int warp = blockIdx.x * (blockDim.x >> 5) + (threadIdx.x >> 5);
    if (warp >= N_NODES) return;
    const int n = warp;
    if (!g_z.need[n]) return;
    const int lane = threadIdx.x & 31;

    const float dn = g_dinv[n];
    float2 a0 = make_float2(0.f, 0.f), a1 = a0, a2 = a0, a3 = a0;

    // self loop
    {
        int   v = x[n];
        uint4 r = g_EW1h[v * 32 + lane];
        acc8(a0, a1, a2, a3, dn * dn, r);
    }

    const int e0 = g_rowstart[n];
    const int e1 = g_rowstart[n + 1];
    int e = e0;
    for (; e + 2 <= e1; e += 2) {
        int2 pa = g_csr[e];
        int2 pb = g_csr[e + 1];
        uint4 ra = g_EW1h[(pa.x >> 20) * 32 + lane];   // independent loads
        uint4 rb = g_EW1h[(pb.x >> 20) * 32 + lane];
        acc8(a0, a1, a2, a3, __int_as_float(pa.y), ra);
        acc8(a0, a1, a2, a3, __int_as_float(pb.y), rb);
    }
    if (e < e1) {
        int2 pa = g_csr[e];
        uint4 ra = g_EW1h[(pa.x >> 20) * 32 + lane];
        acc8(a0, a1, a2, a3, __int_as_float(pa.y), ra);
    }

    const float2* B2 = reinterpret_cast<const float2*>(b1);
    float2 bb0 = B2[lane * 4 + 0], bb1 = B2[lane * 4 + 1];
    float2 bb2 = B2[lane * 4 + 2], bb3 = B2[lane * 4 + 3];
    a0.x = fmaxf(a0.x + bb0.x, 0.f); a0.y = fmaxf(a0.y + bb0.y, 0.f);
    a1.x = fmaxf(a1.x + bb1.x, 0.f); a1.y = fmaxf(a1.y + bb1.y, 0.f);
    a2.x = fmaxf(a2.x + bb2.x, 0.f); a2.y = fmaxf(a2.y + bb2.y, 0.f);
    a3.x = fmaxf(a3.x + bb3.x, 0.f); a3.y = fmaxf(a3.y + bb3.y, 0.f);

    uint4 o;
    *reinterpret_cast<__half2*>(&o.x) = __float22half2_rn(a0);
    *reinterpret_cast<__half2*>(&o.y) = __float22half2_rn(a1);
    *reinterpret_cast<__half2*>(&o.z) = __float22half2_rn(a2);
    *reinterpret_cast<__half2*>(&o.w) = __float22half2_rn(a3);
    g_h1h[(size_t)n * 32 + lane] = o;
}

// ---------------- layer 2: agg(fp16 h1, x4 unroll) -> f32x2 GEMM -> lsm ----
__global__ void __launch_bounds__(256) k_layer2(const int* __restrict__ mask,
                                                const float* __restrict__ W2,
                                                const float* __restrict__ b2,
                                                float* __restrict__ out) {
    __shared__ unsigned long long sagg2[DIM * SAGG_STRIDE];  // 20 KB
    const int t  = threadIdx.x;
    const int r0 = blockIdx.x * R2;
    const __half* H = reinterpret_cast<const __half*>(g_h1h);

    // ---- stage A: aggregate h1 rows; thread t owns feature dim t ----
    float a[R2];
    for (int i = 0; i < R2; i++) {
        const int m  = mask[r0 + i];
        const float dm = g_dinv[m];
        float acc = dm * dm * __half2float(H[(size_t)m * DIM + t]);
        const int e0 = g_rowstart[m];
        const int e1 = g_rowstart[m + 1];
        int e = e0;
        for (; e + 4 <= e1; e += 4) {
            int2 p0 = g_csr[e];
            int2 p1 = g_csr[e + 1];
            int2 p2 = g_csr[e + 2];
            int2 p3 = g_csr[e + 3];
            float h0 = __half2float(H[(size_t)(p0.x & 0xFFFFF) * DIM + t]);
            float h1 = __half2float(H[(size_t)(p1.x & 0xFFFFF) * DIM + t]);
            float h2 = __half2float(H[(size_t)(p2.x & 0xFFFFF) * DIM + t]);
            float h3 = __half2float(H[(size_t)(p3.x & 0xFFFFF) * DIM + t]);
            acc = fmaf(__int_as_float(p0.y), h0, acc);
            acc = fmaf(__int_as_float(p1.y), h1, acc);
            acc = fmaf(__int_as_float(p2.y), h2, acc);
            acc = fmaf(__int_as_float(p3.y), h3, acc);
        }
        for (; e < e1; e++) {
            int2 pw = g_csr[e];
            acc = fmaf(__int_as_float(pw.y),
                       __half2float(H[(size_t)(pw.x & 0xFFFFF) * DIM + t]), acc);
        }
        a[i] = acc;
    }
#pragma unroll
    for (int j = 0; j < 8; j++)
        sagg2[t * SAGG_STRIDE + j] = pk2(a[2 * j], a[2 * j + 1]);
    __syncthreads();

    // ---- stage B: packed f32x2 GEMM ----
    unsigned long long o2[8];
    {
        const float bb = b2[t];
        unsigned long long bbp = pk2(bb, bb);
#pragma unroll
        for (int j = 0; j < 8; j++) o2[j] = bbp;
    }
#pragma unroll 4
    for (int k = 0; k < DIM; k++) {
        const float w = W2[k * DIM + t];
        const unsigned long long ww = pk2(w, w);
        const ulonglong2* A2 = reinterpret_cast<const ulonglong2*>(sagg2 + k * SAGG_STRIDE);
        ulonglong2 p0 = A2[0], p1 = A2[1], p2 = A2[2], p3 = A2[3];
        fma2p(o2[0], p0.x, ww); fma2p(o2[1], p0.y, ww);
        fma2p(o2[2], p1.x, ww); fma2p(o2[3], p1.y, ww);
        fma2p(o2[4], p2.x, ww); fma2p(o2[5], p2.y, ww);
        fma2p(o2[6], p3.x, ww); fma2p(o2[7], p3.y, ww);
    }
    __syncthreads();

    float* sout = reinterpret_cast<float*>(sagg2);   // 16 KB <= 20 KB
#pragma unroll
    for (int j = 0; j < 8; j++) {
        float2 f = upk2(o2[j]);
        sout[(2 * j) * DIM + t]     = f.x;
        sout[(2 * j + 1) * DIM + t] = f.y;
    }
    __syncthreads();

    // ---- stage C: per-row log_softmax ----
    const int wi   = t >> 5;
    const int lane = t & 31;
#pragma unroll
    for (int rr = 0; rr < 2; rr++) {
        const int i = wi + rr * 8;
        float v[8];
        float mx = -INFINITY;
#pragma unroll
        for (int j = 0; j < 8; j++) {
            v[j] = sout[i * DIM + lane + j * 32];
            mx = fmaxf(mx, v[j]);
        }
#pragma unroll
        for (int off = 16; off > 0; off >>= 1)
            mx = fmaxf(mx, __shfl_xor_sync(0xFFFFFFFFu, mx, off));
        float s = 0.f;
#pragma unroll
        for (int j = 0; j < 8; j++) s += expf(v[j] - mx);
#pragma unroll
        for (int off = 16; off > 0; off >>= 1)
            s += __shfl_xor_sync(0xFFFFFFFFu, s, off);
        const float lse = mx + logf(s);
        float* orow = out + (size_t)(r0 + i) * DIM;
#pragma unroll
        for (int j = 0; j < 8; j++) orow[lane + j * 32] = v[j] - lse;
    }
}

// ---------------- launch ----------------
extern "C" void kernel_launch(void* const* d_in, const int* in_sizes, int n_in,
                              void* d_out, int out_size) {
    const int*   x    = (const int*)d_in[0];
    const int*   esrc = (const int*)d_in[1];
    const int*   edst = ((const int*)d_in[1]) + N_EDGES;
    const int*   mask = (const int*)d_in[2];
    const float* emb  = (const float*)d_in[3];
    const float* W1   = (const float*)d_in[4];
    const float* b1   = (const float*)d_in[5];
    const float* W2   = (const float*)d_in[6];
    const float* b2   = (const float*)d_in[7];
    float*       out  = (float*)d_out;

    void* p_z = nullptr;
    cudaGetSymbolAddress(&p_z, g_z);
    cudaMemsetAsync(p_z, 0, sizeof(ZeroRegion), 0);

    const int TB = 256;
    k_hist<<<(N_EDGES + TB - 1) / TB, TB>>>(edst);
    k_blocksum<<<NBLK, SCAN_B>>>();
    k_scanblocks<<<1, 128>>>();
    k_scanfinal<<<NBLK, SCAN_B>>>();
    k_fill<<<(N_EDGES + TB - 1) / TB, TB>>>(esrc, edst, x);
    k_mark<<<(N_MASK + 7) / 8, 256>>>(mask);
    k_ew1<<<VOCAB / EW_ROWS, DIM>>>(emb, W1);
    k_layer1<<<(N_NODES + 7) / 8, 256>>>(x, b1);
    k_layer2<<<N_MASK / R2, 256>>>(mask, W2, b2, out);
}